// round 4
// baseline (speedup 1.0000x reference)
#include <cuda_runtime.h>
#include <math.h>

#define B 8
#define N 2048
#define C 128
#define F 128
#define GALPHA 0.2f
#define NCH 64
#define CH 32    /* N / NCH */

__device__ float g_h[B*N*F];
__device__ float g_e1[B*N], g_e2[B*N];
__device__ float g_P1[B*N], g_N1[B*N];
__device__ int   g_perm[B*N];
__device__ float g_sp2[B*N], g_sn2[B*N]; // sorted exp(e2), exp(0.2*e2)
__device__ float g_offP[B*(NCH+1)*F];    // chunk totals -> exclusive offsets (P2*h)
__device__ float g_offN[B*(NCH+1)*F];
__device__ float g_soffP[B*(NCH+1)];     // scalar chunk totals -> offsets
__device__ float g_soffN[B*(NCH+1)];
__device__ int   g_kk[B*N];              // per-row threshold index

// ---------------------------------------------------------------------------
// Kernel 1: h = text @ W  (64x128 tile, 256 thr, 4x8 thread tile)
//           + fused per-row e1/e2 + exp tables
// ---------------------------------------------------------------------------
__global__ __launch_bounds__(256) void k_gemm_h(const float* __restrict__ text,
                                                const float* __restrict__ W,
                                                const float* __restrict__ a) {
    __shared__ float a_sh[64][33];
    __shared__ float W_sh[32][128];
    __shared__ float avec[2 * F];

    int t = threadIdx.x;
    int row0 = blockIdx.x * 64;
    if (t < 64) ((float4*)avec)[t] = ((const float4*)a)[t];

    int tx = t & 15, ty = t >> 4;

    float acc[4][8];
#pragma unroll
    for (int r = 0; r < 4; ++r)
#pragma unroll
        for (int k = 0; k < 8; ++k) acc[r][k] = 0.f;

    for (int k0 = 0; k0 < C; k0 += 32) {
#pragma unroll
        for (int i = 0; i < 2; ++i) {
            int idx = t + i * 256;
            int r = idx >> 3, c4 = idx & 7;
            float4 v = *(const float4*)(text + (size_t)(row0 + r) * C + k0 + c4 * 4);
            a_sh[r][c4 * 4 + 0] = v.x;
            a_sh[r][c4 * 4 + 1] = v.y;
            a_sh[r][c4 * 4 + 2] = v.z;
            a_sh[r][c4 * 4 + 3] = v.w;
        }
#pragma unroll
        for (int i = 0; i < 4; ++i) {
            int idx = t + i * 256;
            int kr = idx >> 5, f4 = idx & 31;
            *(float4*)&W_sh[kr][f4 * 4] =
                *(const float4*)(W + (size_t)(k0 + kr) * F + f4 * 4);
        }
        __syncthreads();

#pragma unroll
        for (int jj = 0; jj < 32; ++jj) {
            float4 w0 = *(const float4*)&W_sh[jj][tx * 8];
            float4 w1 = *(const float4*)&W_sh[jj][tx * 8 + 4];
#pragma unroll
            for (int r = 0; r < 4; ++r) {
                float av = a_sh[ty * 4 + r][jj];
                acc[r][0] = fmaf(av, w0.x, acc[r][0]);
                acc[r][1] = fmaf(av, w0.y, acc[r][1]);
                acc[r][2] = fmaf(av, w0.z, acc[r][2]);
                acc[r][3] = fmaf(av, w0.w, acc[r][3]);
                acc[r][4] = fmaf(av, w1.x, acc[r][4]);
                acc[r][5] = fmaf(av, w1.y, acc[r][5]);
                acc[r][6] = fmaf(av, w1.z, acc[r][6]);
                acc[r][7] = fmaf(av, w1.w, acc[r][7]);
            }
        }
        __syncthreads();
    }

#pragma unroll
    for (int r = 0; r < 4; ++r) {
        int row = row0 + ty * 4 + r;
        size_t gi = (size_t)row * F + tx * 8;
        float4 o0 = {acc[r][0], acc[r][1], acc[r][2], acc[r][3]};
        float4 o1 = {acc[r][4], acc[r][5], acc[r][6], acc[r][7]};
        *(float4*)(g_h + gi) = o0;
        *(float4*)(g_h + gi + 4) = o1;

        float p1 = 0.f, p2 = 0.f;
#pragma unroll
        for (int k = 0; k < 8; ++k) {
            p1 = fmaf(acc[r][k], avec[tx * 8 + k], p1);
            p2 = fmaf(acc[r][k], avec[F + tx * 8 + k], p2);
        }
#pragma unroll
        for (int o = 8; o > 0; o >>= 1) {
            p1 += __shfl_xor_sync(0xffffffffu, p1, o);
            p2 += __shfl_xor_sync(0xffffffffu, p2, o);
        }
        if (tx == 0) {
            g_e1[row] = p1;
            g_e2[row] = p2;
            g_P1[row] = expf(p1);
            g_N1[row] = expf(GALPHA * p1);
        }
    }
}

// ---------------------------------------------------------------------------
// Kernel 2: per-batch bitonic sort of (-e2) ascending with index payload.
// Epilogue: sorted exp tables + per-row threshold index (binary search in smem)
// ---------------------------------------------------------------------------
__global__ __launch_bounds__(1024) void k_sort() {
    __shared__ float key[N];
    __shared__ int   sid[N];
    int b = blockIdx.x, t = threadIdx.x;

    for (int j = t; j < N; j += 1024) { key[j] = -g_e2[b * N + j]; sid[j] = j; }
    __syncthreads();

    for (int k2 = 2; k2 <= N; k2 <<= 1) {
        for (int j2 = k2 >> 1; j2 > 0; j2 >>= 1) {
            for (int tt = t; tt < N; tt += 1024) {
                int ixj = tt ^ j2;
                if (ixj > tt) {
                    bool up = ((tt & k2) == 0);
                    float ka = key[tt], kb = key[ixj];
                    if ((ka > kb) == up) {
                        key[tt] = kb; key[ixj] = ka;
                        int tmp = sid[tt]; sid[tt] = sid[ixj]; sid[ixj] = tmp;
                    }
                }
            }
            __syncthreads();
        }
    }

    for (int j = t; j < N; j += 1024) {
        float kv = key[j];
        g_perm[b * N + j] = sid[j];
        g_sp2[b * N + j] = expf(-kv);           // P2 = exp(e2)
        g_sn2[b * N + j] = expf(-GALPHA * kv);  // N2 = exp(0.2*e2)
    }

    // threshold index: first idx with key[idx] >= e1_row
    for (int row = t; row < N; row += 1024) {
        float e1 = g_e1[b * N + row];
        int lo = 0, hi = N;
        while (lo < hi) {
            int m = (lo + hi) >> 1;
            if (key[m] < e1) lo = m + 1; else hi = m;
        }
        g_kk[b * N + row] = lo;
    }
}

// ---------------------------------------------------------------------------
// Kernel 3: per-chunk totals (vector + scalar), reading h via perm gather
// ---------------------------------------------------------------------------
__global__ __launch_bounds__(128) void k_chunktot() {
    int c = blockIdx.x, b = blockIdx.y, f = threadIdx.x;
    int j0 = b * N + c * CH;

    float tp = 0.f, tn = 0.f, sps = 0.f, sns = 0.f;
#pragma unroll 8
    for (int jj = 0; jj < CH; ++jj) {
        int j = j0 + jj;
        int r = g_perm[j];
        float wp = g_sp2[j], wn = g_sn2[j];
        float hv = g_h[((size_t)(b * N + r)) * F + f];
        tp = fmaf(wp, hv, tp);
        tn = fmaf(wn, hv, tn);
        sps += wp; sns += wn;
    }
    size_t ob = ((size_t)(b * (NCH + 1) + c)) * F + f;
    g_offP[ob] = tp;
    g_offN[ob] = tn;
    if (f == 0) {
        g_soffP[b * (NCH + 1) + c] = sps;
        g_soffN[b * (NCH + 1) + c] = sns;
    }
}

// ---------------------------------------------------------------------------
// Kernel 4: exclusive scan over 64 chunk totals.
// Vector: register-preloaded (64 independent LDGs -> one latency round-trip).
// Scalar: warp-parallel shfl scan (warp0 = P, warp1 = N).
// ---------------------------------------------------------------------------
__global__ __launch_bounds__(128) void k_chunkscan() {
    int b = blockIdx.x, f = threadIdx.x;
    size_t ob = (size_t)b * (NCH + 1) * F + f;

    {   // vector P
        float v[NCH];
#pragma unroll
        for (int c = 0; c < NCH; ++c) v[c] = g_offP[ob + (size_t)c * F];
        float acc = 0.f;
#pragma unroll
        for (int c = 0; c < NCH; ++c) {
            float tv = v[c];
            g_offP[ob + (size_t)c * F] = acc;
            acc += tv;
        }
        g_offP[ob + (size_t)NCH * F] = acc;
    }
    {   // vector N
        float v[NCH];
#pragma unroll
        for (int c = 0; c < NCH; ++c) v[c] = g_offN[ob + (size_t)c * F];
        float acc = 0.f;
#pragma unroll
        for (int c = 0; c < NCH; ++c) {
            float tv = v[c];
            g_offN[ob + (size_t)c * F] = acc;
            acc += tv;
        }
        g_offN[ob + (size_t)NCH * F] = acc;
    }

    // scalar scans: 64 values each, two halves of 32 per warp
    int w = f >> 5, lane = f & 31;
    if (w < 2) {
        float* arr = (w == 0) ? g_soffP : g_soffN;
        size_t o = (size_t)b * (NCH + 1);
        float p0 = arr[o + lane];
        float p1 = arr[o + 32 + lane];
        float i0 = p0, i1 = p1;
#pragma unroll
        for (int off = 1; off < 32; off <<= 1) {
            float u0 = __shfl_up_sync(0xffffffffu, i0, off);
            float u1 = __shfl_up_sync(0xffffffffu, i1, off);
            if (lane >= off) { i0 += u0; i1 += u1; }
        }
        float tot0 = __shfl_sync(0xffffffffu, i0, 31);
        float tot1 = __shfl_sync(0xffffffffu, i1, 31);
        arr[o + lane] = i0 - p0;                 // exclusive, first half
        arr[o + 32 + lane] = tot0 + i1 - p1;     // exclusive, second half
        if (lane == 31) arr[o + NCH] = tot0 + tot1;
    }
}

// ---------------------------------------------------------------------------
// Kernel 5: per-row output: chunk offset + <=32-element tail + elu epilogue
// ---------------------------------------------------------------------------
__global__ __launch_bounds__(128) void k_out(float* __restrict__ out) {
    __shared__ int   kk[32];
    __shared__ float p1s[32], n1s[32];

    int t = threadIdx.x;
    int b = blockIdx.y;
    int i0 = blockIdx.x * 32;

    if (t < 32) {
        int i = b * N + i0 + t;
        kk[t] = g_kk[i];
        p1s[t] = g_P1[i];
        n1s[t] = g_N1[i];
    }
    __syncthreads();

    float totNf = g_offN[((size_t)(b * (NCH + 1) + NCH)) * F + t];
    float totNs = g_soffN[b * (NCH + 1) + NCH];

#pragma unroll 2
    for (int r = 0; r < 32; ++r) {
        int k = kk[r];
        int c = k >> 5;
        int m = k & 31;
        size_t ob = ((size_t)(b * (NCH + 1) + c)) * F + t;
        float SPf = g_offP[ob];
        float SNf = g_offN[ob];
        float sPs = g_soffP[b * (NCH + 1) + c];
        float sNs = g_soffN[b * (NCH + 1) + c];

        int jb = b * N + (c << 5);
        for (int jj = 0; jj < m; ++jj) {
            float wp = g_sp2[jb + jj];
            float wn = g_sn2[jb + jj];
            int rw = g_perm[jb + jj];
            float hv = g_h[((size_t)(b * N + rw)) * F + t];
            SPf = fmaf(wp, hv, SPf);
            SNf = fmaf(wn, hv, SNf);
            sPs += wp; sNs += wn;
        }

        float P1 = p1s[r], N1v = n1s[r];
        float den = fmaf(P1, sPs, N1v * (totNs - sNs));
        float num = fmaf(P1, SPf, N1v * (totNf - SNf));
        float hv_i = g_h[((size_t)(b * N + i0 + r)) * F + t];
        float x = num / den + GALPHA * hv_i;
        out[((size_t)(b * N + i0 + r)) * F + t] = (x > 0.f) ? x : expm1f(x);
    }
}

extern "C" void kernel_launch(void* const* d_in, const int* in_sizes, int n_in,
                              void* d_out, int out_size) {
    const float* text = (const float*)d_in[0];
    // d_in[1] = adj : unused by the reference computation
    const float* W = (const float*)d_in[2];
    const float* a = (const float*)d_in[3];
    float* out = (float*)d_out;

    k_gemm_h<<<(B * N) / 64, 256>>>(text, W, a);
    k_sort<<<B, 1024>>>();
    dim3 gct(NCH, B);
    k_chunktot<<<gct, 128>>>();
    k_chunkscan<<<B, 128>>>();
    dim3 go(N / 32, B);
    k_out<<<go, 128>>>(out);
}

// round 5
// speedup vs baseline: 2.0079x; 2.0079x over previous
#include <cuda_runtime.h>
#include <math.h>

#define B 8
#define N 2048
#define C 128
#define F 128
#define GALPHA 0.2f
#define NCH 64
#define CH 32    /* N / NCH */

__device__ float g_h[B*N*F];
__device__ float g_e1[B*N], g_e2[B*N];
__device__ float g_P1[B*N], g_N1[B*N];
__device__ int   g_perm[B*N];
__device__ float g_sp2[B*N], g_sn2[B*N];   // sorted exp(e2), exp(0.2*e2)
__device__ float g_ctP[B*NCH*F];           // vector chunk totals
__device__ float g_ctN[B*NCH*F];
__device__ float g_SP[B*(N+1)*F];          // full exclusive prefix of P2*h (sorted)
__device__ float g_SN[B*(N+1)*F];
__device__ float g_sP[B*(N+1)];            // scalar exclusive prefixes
__device__ float g_sN[B*(N+1)];
__device__ int   g_kk[B*N];                // per-row threshold index

// ---------------------------------------------------------------------------
// Kernel 1: h = text @ W  (64x128 tile, 256 thr, 4x8 thread tile)
//           + fused per-row e1/e2 + exp tables
// ---------------------------------------------------------------------------
__global__ __launch_bounds__(256) void k_gemm_h(const float* __restrict__ text,
                                                const float* __restrict__ W,
                                                const float* __restrict__ a) {
    __shared__ float a_sh[64][33];
    __shared__ float W_sh[32][128];
    __shared__ float avec[2 * F];

    int t = threadIdx.x;
    int row0 = blockIdx.x * 64;
    if (t < 64) ((float4*)avec)[t] = ((const float4*)a)[t];

    int tx = t & 15, ty = t >> 4;

    float acc[4][8];
#pragma unroll
    for (int r = 0; r < 4; ++r)
#pragma unroll
        for (int k = 0; k < 8; ++k) acc[r][k] = 0.f;

    for (int k0 = 0; k0 < C; k0 += 32) {
#pragma unroll
        for (int i = 0; i < 2; ++i) {
            int idx = t + i * 256;
            int r = idx >> 3, c4 = idx & 7;
            float4 v = *(const float4*)(text + (size_t)(row0 + r) * C + k0 + c4 * 4);
            a_sh[r][c4 * 4 + 0] = v.x;
            a_sh[r][c4 * 4 + 1] = v.y;
            a_sh[r][c4 * 4 + 2] = v.z;
            a_sh[r][c4 * 4 + 3] = v.w;
        }
#pragma unroll
        for (int i = 0; i < 4; ++i) {
            int idx = t + i * 256;
            int kr = idx >> 5, f4 = idx & 31;
            *(float4*)&W_sh[kr][f4 * 4] =
                *(const float4*)(W + (size_t)(k0 + kr) * F + f4 * 4);
        }
        __syncthreads();

#pragma unroll
        for (int jj = 0; jj < 32; ++jj) {
            float4 w0 = *(const float4*)&W_sh[jj][tx * 8];
            float4 w1 = *(const float4*)&W_sh[jj][tx * 8 + 4];
#pragma unroll
            for (int r = 0; r < 4; ++r) {
                float av = a_sh[ty * 4 + r][jj];
                acc[r][0] = fmaf(av, w0.x, acc[r][0]);
                acc[r][1] = fmaf(av, w0.y, acc[r][1]);
                acc[r][2] = fmaf(av, w0.z, acc[r][2]);
                acc[r][3] = fmaf(av, w0.w, acc[r][3]);
                acc[r][4] = fmaf(av, w1.x, acc[r][4]);
                acc[r][5] = fmaf(av, w1.y, acc[r][5]);
                acc[r][6] = fmaf(av, w1.z, acc[r][6]);
                acc[r][7] = fmaf(av, w1.w, acc[r][7]);
            }
        }
        __syncthreads();
    }

#pragma unroll
    for (int r = 0; r < 4; ++r) {
        int row = row0 + ty * 4 + r;
        size_t gi = (size_t)row * F + tx * 8;
        float4 o0 = {acc[r][0], acc[r][1], acc[r][2], acc[r][3]};
        float4 o1 = {acc[r][4], acc[r][5], acc[r][6], acc[r][7]};
        *(float4*)(g_h + gi) = o0;
        *(float4*)(g_h + gi + 4) = o1;

        float p1 = 0.f, p2 = 0.f;
#pragma unroll
        for (int k = 0; k < 8; ++k) {
            p1 = fmaf(acc[r][k], avec[tx * 8 + k], p1);
            p2 = fmaf(acc[r][k], avec[F + tx * 8 + k], p2);
        }
#pragma unroll
        for (int o = 8; o > 0; o >>= 1) {
            p1 += __shfl_xor_sync(0xffffffffu, p1, o);
            p2 += __shfl_xor_sync(0xffffffffu, p2, o);
        }
        if (tx == 0) {
            g_e1[row] = p1;
            g_e2[row] = p2;
            g_P1[row] = expf(p1);
            g_N1[row] = expf(GALPHA * p1);
        }
    }
}

// ---------------------------------------------------------------------------
// Kernel 2: per-batch bitonic sort of (-e2) ascending with index payload.
// Epilogue: sorted exp tables, scalar exclusive prefix scans, threshold idx.
// ---------------------------------------------------------------------------
__global__ __launch_bounds__(1024) void k_sort() {
    __shared__ float key[N];
    __shared__ int   sid[N];
    __shared__ float s1[N], s2[N];
    int b = blockIdx.x, t = threadIdx.x;

    for (int j = t; j < N; j += 1024) { key[j] = -g_e2[b * N + j]; sid[j] = j; }
    __syncthreads();

    for (int k2 = 2; k2 <= N; k2 <<= 1) {
        for (int j2 = k2 >> 1; j2 > 0; j2 >>= 1) {
            for (int tt = t; tt < N; tt += 1024) {
                int ixj = tt ^ j2;
                if (ixj > tt) {
                    bool up = ((tt & k2) == 0);
                    float ka = key[tt], kb = key[ixj];
                    if ((ka > kb) == up) {
                        key[tt] = kb; key[ixj] = ka;
                        int tmp = sid[tt]; sid[tt] = sid[ixj]; sid[ixj] = tmp;
                    }
                }
            }
            __syncthreads();
        }
    }

    // exp tables (global + smem for scan)
    int j0 = t, j1 = t + 1024;
    float p20 = expf(-key[j0]), p21 = expf(-key[j1]);
    float n20 = expf(-GALPHA * key[j0]), n21 = expf(-GALPHA * key[j1]);
    g_perm[b * N + j0] = sid[j0];  g_perm[b * N + j1] = sid[j1];
    g_sp2[b * N + j0] = p20;       g_sp2[b * N + j1] = p21;
    g_sn2[b * N + j0] = n20;       g_sn2[b * N + j1] = n21;
    s1[j0] = p20; s1[j1] = p21;
    s2[j0] = n20; s2[j1] = n21;
    __syncthreads();

    // Hillis-Steele inclusive scan of s1/s2 over 2048 elements
#pragma unroll
    for (int off = 1; off < N; off <<= 1) {
        float a0 = 0.f, a1 = 0.f, c0 = 0.f, c1 = 0.f;
        if (j0 >= off) { a0 = s1[j0 - off]; c0 = s2[j0 - off]; }
        if (j1 >= off) { a1 = s1[j1 - off]; c1 = s2[j1 - off]; }
        __syncthreads();
        s1[j0] += a0; s2[j0] += c0;
        s1[j1] += a1; s2[j1] += c1;
        __syncthreads();
    }
    size_t o = (size_t)b * (N + 1);
    g_sP[o + j0] = s1[j0] - p20;  g_sP[o + j1] = s1[j1] - p21;
    g_sN[o + j0] = s2[j0] - n20;  g_sN[o + j1] = s2[j1] - n21;
    if (t == 1023) { g_sP[o + N] = s1[N - 1]; g_sN[o + N] = s2[N - 1]; }

    // threshold index: first idx with key[idx] >= e1_row
    for (int row = t; row < N; row += 1024) {
        float e1 = g_e1[b * N + row];
        int lo = 0, hi = N;
        while (lo < hi) {
            int m = (lo + hi) >> 1;
            if (key[m] < e1) lo = m + 1; else hi = m;
        }
        g_kk[b * N + row] = lo;
    }
}

// ---------------------------------------------------------------------------
// Kernel 3: per-chunk vector totals (perm preloaded -> batched h gathers)
// ---------------------------------------------------------------------------
__global__ __launch_bounds__(128) void k_ctot() {
    int c = blockIdx.x, b = blockIdx.y, f = threadIdx.x;
    int jb = b * N + c * CH;

    int rw[CH];
#pragma unroll
    for (int jj = 0; jj < CH; ++jj) rw[jj] = g_perm[jb + jj];

    float tp = 0.f, tn = 0.f;
#pragma unroll
    for (int jj = 0; jj < CH; ++jj) {
        float hv = g_h[((size_t)(b * N + rw[jj])) * F + f];
        tp = fmaf(g_sp2[jb + jj], hv, tp);
        tn = fmaf(g_sn2[jb + jj], hv, tn);
    }
    size_t ob = ((size_t)(b * NCH + c)) * F + f;
    g_ctP[ob] = tp;
    g_ctN[ob] = tn;
}

// ---------------------------------------------------------------------------
// Kernel 4: per-chunk offset (independent reg-sum of preceding totals)
//           + recompute products + write full exclusive prefixes
// ---------------------------------------------------------------------------
__global__ __launch_bounds__(128) void k_scanlocal() {
    int c = blockIdx.x, b = blockIdx.y, f = threadIdx.x;

    size_t ctb = ((size_t)b * NCH) * F + f;
    float offP = 0.f, offN = 0.f;
    for (int cc = 0; cc < c; ++cc) {
        offP += g_ctP[ctb + (size_t)cc * F];
        offN += g_ctN[ctb + (size_t)cc * F];
    }

    int jb = b * N + c * CH;
    int rw[CH];
#pragma unroll
    for (int jj = 0; jj < CH; ++jj) rw[jj] = g_perm[jb + jj];
    float wp[CH], wn[CH];
#pragma unroll
    for (int jj = 0; jj < CH; ++jj) { wp[jj] = g_sp2[jb + jj]; wn[jj] = g_sn2[jb + jj]; }

    float accP = offP, accN = offN;
    size_t sb = ((size_t)(b * (N + 1) + c * CH)) * F + f;
#pragma unroll
    for (int jj = 0; jj < CH; ++jj) {
        float hv = g_h[((size_t)(b * N + rw[jj])) * F + f];
        g_SP[sb + (size_t)jj * F] = accP;
        g_SN[sb + (size_t)jj * F] = accN;
        accP = fmaf(wp[jj], hv, accP);
        accN = fmaf(wn[jj], hv, accN);
    }
    if (c == NCH - 1) {
        g_SP[((size_t)(b * (N + 1) + N)) * F + f] = accP;
        g_SN[((size_t)(b * (N + 1) + N)) * F + f] = accN;
    }
}

// ---------------------------------------------------------------------------
// Kernel 5: per-row O(1) lookup + elu epilogue
// ---------------------------------------------------------------------------
__global__ __launch_bounds__(128) void k_out(float* __restrict__ out) {
    __shared__ int   kk[32];
    __shared__ float p1s[32], n1s[32], sps[32], sns[32];

    int t = threadIdx.x;
    int b = blockIdx.y;
    int i0 = blockIdx.x * 32;

    if (t < 32) {
        int i = b * N + i0 + t;
        int k = g_kk[i];
        kk[t] = k;
        p1s[t] = g_P1[i];
        n1s[t] = g_N1[i];
        sps[t] = g_sP[(size_t)b * (N + 1) + k];
        sns[t] = g_sN[(size_t)b * (N + 1) + k];
    }
    __syncthreads();

    float totNf = g_SN[((size_t)(b * (N + 1) + N)) * F + t];
    float totNs = g_sN[(size_t)b * (N + 1) + N];

#pragma unroll 4
    for (int r = 0; r < 32; ++r) {
        int k = kk[r];
        size_t sb = ((size_t)(b * (N + 1) + k)) * F + t;
        float SPf = g_SP[sb];
        float SNf = g_SN[sb];

        float P1 = p1s[r], N1v = n1s[r];
        float den = fmaf(P1, sps[r], N1v * (totNs - sns[r]));
        float num = fmaf(P1, SPf, N1v * (totNf - SNf));
        float hv_i = g_h[((size_t)(b * N + i0 + r)) * F + t];
        float x = num / den + GALPHA * hv_i;
        out[((size_t)(b * N + i0 + r)) * F + t] = (x > 0.f) ? x : expm1f(x);
    }
}

extern "C" void kernel_launch(void* const* d_in, const int* in_sizes, int n_in,
                              void* d_out, int out_size) {
    const float* text = (const float*)d_in[0];
    // d_in[1] = adj : unused by the reference computation
    const float* W = (const float*)d_in[2];
    const float* a = (const float*)d_in[3];
    float* out = (float*)d_out;

    k_gemm_h<<<(B * N) / 64, 256>>>(text, W, a);
    k_sort<<<B, 1024>>>();
    dim3 gc(NCH, B);
    k_ctot<<<gc, 128>>>();
    k_scanlocal<<<gc, 128>>>();
    dim3 go(N / 32, B);
    k_out<<<go, 128>>>(out);
}